// round 15
// baseline (speedup 1.0000x reference)
#include <cuda_runtime.h>
#include <cuda_fp16.h>
#include <math.h>
#include <stdint.h>

#define SEQ 2048
#define DM  1024
#define NH  16
#define DH  64
#define SS  ((long)SEQ * SEQ)

#define SRS  144   // 64 fp16 = 128B data + 16B pad (GEMM staging row stride)
#define OSTR 272   // 128 fp16 = 256B data + 16B pad (output staging row stride)

// ---------------- scratch (device globals; no allocations allowed) ----------
__device__ __half g_bds[(size_t)NH * SEQ * SEQ];            // B_D_hat (unshifted), fp16
__device__ __half g_ac[(size_t)NH * SEQ * SEQ];             // A_C scores, fp16
__device__ __half g_w16[(size_t)NH * SEQ * SEQ];            // softmax weights, fp16

__device__ __half g_xq16[SEQ * DM], g_xkey16[SEQ * DM], g_xv16[SEQ * DM], g_re16[SEQ * DM];
__device__ __half g_wq16[DM * DM], g_wke16[DM * DM], g_wkr16[DM * DM];
__device__ __half g_wv16[DM * DM], g_wf16[DM * DM];

__device__ __half g_qu16[SEQ * DM], g_qv16[SEQ * DM];
__device__ __half g_k16[SEQ * DM],  g_qr16[SEQ * DM];

__device__ __half g_v16T[DM * SEQ];                          // [n=h*64+d][f]
__device__ __half g_o116[SEQ * DM];

__device__ int g_headmax[NH];

// ---------------- helpers ----------------------------------------------------
__device__ __forceinline__ uint32_t smem_u32(const void* p) {
    uint32_t a;
    asm("{ .reg .u64 t; cvta.to.shared.u64 t, %1; cvt.u32.u64 %0, t; }" : "=r"(a) : "l"(p));
    return a;
}
__device__ __forceinline__ void cp16(uint32_t s, const void* g) {
    asm volatile("cp.async.cg.shared.global [%0], [%1], 16;" :: "r"(s), "l"(g));
}
__device__ __forceinline__ void cp_commit() {
    asm volatile("cp.async.commit_group;" ::: "memory");
}
template <int N>
__device__ __forceinline__ void cp_wait() {
    asm volatile("cp.async.wait_group %0;" :: "n"(N) : "memory");
}
__device__ __forceinline__ void ldmx4(uint32_t* r, uint32_t addr) {
    asm volatile("ldmatrix.sync.aligned.m8n8.x4.shared.b16 {%0,%1,%2,%3}, [%4];"
                 : "=r"(r[0]), "=r"(r[1]), "=r"(r[2]), "=r"(r[3]) : "r"(addr));
}
__device__ __forceinline__ void mma_f16(float* c, const uint32_t* a, uint32_t b0, uint32_t b1) {
    asm volatile("mma.sync.aligned.m16n8k16.row.col.f32.f16.f16.f32 "
                 "{%0,%1,%2,%3}, {%4,%5,%6,%7}, {%8,%9}, {%0,%1,%2,%3};"
                 : "+f"(c[0]), "+f"(c[1]), "+f"(c[2]), "+f"(c[3])
                 : "r"(a[0]), "r"(a[1]), "r"(a[2]), "r"(a[3]), "r"(b0), "r"(b1));
}
__device__ __forceinline__ float wred_max(float v) {
#pragma unroll
    for (int o = 16; o; o >>= 1) v = fmaxf(v, __shfl_xor_sync(0xFFFFFFFFu, v, o));
    return v;
}
__device__ __forceinline__ float wred_sum(float v) {
#pragma unroll
    for (int o = 16; o; o >>= 1) v += __shfl_xor_sync(0xFFFFFFFFu, v, o);
    return v;
}

struct alignas(8) H4 { __half v[4]; };

// ---------------- merged elementwise fp16 convert + relenc -------------------
__global__ __launch_bounds__(256) void split_all(
    const float* __restrict__ q, const float* __restrict__ k, const float* __restrict__ v,
    const float* __restrict__ wq, const float* __restrict__ wke, const float* __restrict__ wkr,
    const float* __restrict__ wv, const float* __restrict__ wf)
{
    int z = blockIdx.z;
    long i = ((long)blockIdx.x * 256 + threadIdx.x) * 4;
    if (z == 8) {   // relative positional encoding (+ headmax init)
        if (blockIdx.x == 0 && threadIdx.x < NH) g_headmax[threadIdx.x] = 0;
        if (i >= (long)SEQ * DM) return;
        int f = (int)(i / DM), c0 = (int)(i % DM);
        float p = (float)(SEQ - 1 - f);
        H4 o;
#pragma unroll
        for (int t = 0; t < 4; t++) {
            int c = c0 + t;
            float e  = (float)(c & ~1) * (1.0f / (float)DM);
            float dv = exp2f(-e * 13.287712379549449f);    // log2(10000)
            float ang = p * dv;
            float s, cs; sincosf(ang, &s, &cs);
            o.v[t] = __float2half((c & 1) ? cs : s);
        }
        *(H4*)(g_re16 + i) = o;
        return;
    }
    long n = (z < 3) ? (long)SEQ * DM : (long)DM * DM;
    if (i >= n) return;
    const float* src; __half* dst;
    switch (z) {
        case 0: src = q;   dst = g_xq16;   break;
        case 1: src = k;   dst = g_xkey16; break;
        case 2: src = v;   dst = g_xv16;   break;
        case 3: src = wq;  dst = g_wq16;   break;
        case 4: src = wke; dst = g_wke16;  break;
        case 5: src = wkr; dst = g_wkr16;  break;
        case 6: src = wv;  dst = g_wv16;   break;
        default: src = wf; dst = g_wf16;   break;
    }
    float4 x = *(const float4*)(src + i);
    H4 o;
    o.v[0] = __float2half(x.x); o.v[1] = __float2half(x.y);
    o.v[2] = __float2half(x.z); o.v[3] = __float2half(x.w);
    *(H4*)(dst + i) = o;
}

// ---------------- generic fp16 HMMA GEMM core --------------------------------
#define E_HALF 0   // H1[m*ldo+n] = half(x)
#define E_DUAL 1   // H1 = half(x+b1[n]), H2 = half(x+b2[n])
#define E_VT   2   // H1[n*ldo+m] = half(x), via smem-staged transpose
#define E_GELU 3   // outF[m*ldo+n] = gelu(x)

template <int BN, int EPI>
__device__ __forceinline__ void f16_core(
    const __half* __restrict__ Ag, int lda,
    const __half* __restrict__ Bg, int ldb, int K,
    float* __restrict__ outF, __half* __restrict__ H1, __half* __restrict__ H2,
    const float* __restrict__ b1, const float* __restrict__ b2, long ldo)
{
    constexpr int NHT = BN / 64;
    constexpr int NJ  = BN / 16;
    constexpr int STG = (128 + BN) * SRS;
    constexpr int OBOFF = 2 * STG;

    extern __shared__ char smem[];
    uint32_t sb = smem_u32(smem);

    int tid = threadIdx.x, lane = tid & 31, w = tid >> 5;
    int wm = w >> 1, wn = w & 1;
    int m0 = blockIdx.y * 128, n0 = blockIdx.x * BN;

    float acc[2][NJ][4];
#pragma unroll
    for (int mi = 0; mi < 2; mi++)
#pragma unroll
        for (int nj = 0; nj < NJ; nj++)
#pragma unroll
            for (int qq = 0; qq < 4; qq++) acc[mi][nj][qq] = 0.0f;

    auto load_stage = [&](int st, int k0) {
        uint32_t s0 = sb + st * STG;
#pragma unroll
        for (int i = 0; i < 4; i++) {
            int idx = tid + i * 256;
            int r = idx >> 3, v = idx & 7;
            cp16(s0 + r * SRS + v * 16, Ag + (long)(m0 + r) * lda + k0 + v * 8);
        }
#pragma unroll
        for (int i = 0; i < BN / 32; i++) {
            int idx = tid + i * 256;
            int r = idx >> 3, v = idx & 7;
            cp16(s0 + 128 * SRS + r * SRS + v * 16, Bg + (long)(n0 + r) * ldb + k0 + v * 8);
        }
        cp_commit();
    };

    auto compute_stage = [&](int st) {
        uint32_t aB = sb + st * STG;
        uint32_t bB = aB + 128 * SRS;
        uint32_t l15 = (uint32_t)(lane & 15);
        uint32_t lh  = (uint32_t)(lane >> 4);
#pragma unroll
        for (int ks = 0; ks < 4; ks++) {
            uint32_t a[2][4];
#pragma unroll
            for (int mi = 0; mi < 2; mi++)
                ldmx4(a[mi], aB + (wm * 32 + mi * 16 + l15) * SRS + ks * 32 + lh * 16);
#pragma unroll
            for (int nh = 0; nh < NHT; nh++) {
                uint32_t b[2][4];
#pragma unroll
                for (int bt = 0; bt < 2; bt++)
                    ldmx4(b[bt], bB + (wn * (BN / 2) + nh * 32 + bt * 16 + l15) * SRS + ks * 32 + lh * 16);
#pragma unroll
                for (int mi = 0; mi < 2; mi++)
#pragma unroll
                    for (int bt = 0; bt < 2; bt++)
#pragma unroll
                        for (int s = 0; s < 2; s++)
                            mma_f16(acc[mi][nh * 4 + bt * 2 + s], a[mi], b[bt][s], b[bt][s + 2]);
            }
        }
    };

    load_stage(0, 0);
    const int nc = K >> 6;
    for (int c = 0; c < nc; c++) {
        if (c + 1 < nc) {
            load_stage((c + 1) & 1, (c + 1) << 6);
            cp_wait<1>();
        } else {
            cp_wait<0>();
        }
        __syncthreads();
        compute_stage(c & 1);
        __syncthreads();
    }

    int rbl = wm * 32 + (lane >> 2);
    int cbl = wn * (BN / 2) + (lane & 3) * 2;

    if (EPI == E_VT) {
#pragma unroll
        for (int mi = 0; mi < 2; mi++)
#pragma unroll
            for (int nj = 0; nj < NJ; nj++)
#pragma unroll
                for (int qq = 0; qq < 4; qq++) {
                    int m_l = rbl + mi * 16 + (qq >> 1) * 8;
                    int n_l = cbl + nj * 8 + (qq & 1);
                    *(__half*)(smem + OBOFF + n_l * OSTR + m_l * 2) =
                        __float2half(acc[mi][nj][qq]);
                }
        __syncthreads();
#pragma unroll
        for (int i = 0; i < 8; i++) {
            int idx = tid + i * 256;
            int r = idx >> 4, ch = idx & 15;
            uint4 vv = *(uint4*)(smem + OBOFF + r * OSTR + ch * 16);
            *(uint4*)(H1 + (long)(n0 + r) * ldo + m0 + ch * 8) = vv;
        }
        return;
    }

#pragma unroll
    for (int mi = 0; mi < 2; mi++)
#pragma unroll
        for (int nj = 0; nj < NJ; nj++) {
            int m = m0 + rbl + mi * 16;
            int n = n0 + cbl + nj * 8;
            float c0 = acc[mi][nj][0], c1 = acc[mi][nj][1];
            float c2 = acc[mi][nj][2], c3 = acc[mi][nj][3];
            if (EPI == E_HALF) {
                *(__half2*)(H1 + (long)m * ldo + n)       = __floats2half2_rn(c0, c1);
                *(__half2*)(H1 + (long)(m + 8) * ldo + n) = __floats2half2_rn(c2, c3);
            } else if (EPI == E_DUAL) {
                float u0 = b1[n], u1 = b1[n + 1], v0 = b2[n], v1 = b2[n + 1];
                *(__half2*)(H1 + (long)m * ldo + n)       = __floats2half2_rn(c0 + u0, c1 + u1);
                *(__half2*)(H1 + (long)(m + 8) * ldo + n) = __floats2half2_rn(c2 + u0, c3 + u1);
                *(__half2*)(H2 + (long)m * ldo + n)       = __floats2half2_rn(c0 + v0, c1 + v1);
                *(__half2*)(H2 + (long)(m + 8) * ldo + n) = __floats2half2_rn(c2 + v0, c3 + v1);
            } else {  // E_GELU
                float2 o0, o1;
                o0.x = 0.5f * c0 * (1.0f + erff(c0 * 0.70710678118654752440f));
                o0.y = 0.5f * c1 * (1.0f + erff(c1 * 0.70710678118654752440f));
                o1.x = 0.5f * c2 * (1.0f + erff(c2 * 0.70710678118654752440f));
                o1.y = 0.5f * c3 * (1.0f + erff(c3 * 0.70710678118654752440f));
                *(float2*)(outF + (long)m * ldo + n)       = o0;
                *(float2*)(outF + (long)(m + 8) * ldo + n) = o1;
            }
        }
}

// ---------------- GEMM wrapper kernels ---------------------------------------
__global__ __launch_bounds__(256) void proj_all16(const float* __restrict__ up,
                                                  const float* __restrict__ vp) {
    int z = blockIdx.z;
    if (z == 0)
        f16_core<128, E_DUAL>(g_xq16, DM, g_wq16, DM, DM,
                              nullptr, g_qu16, g_qv16, up, vp, DM);
    else if (z == 1)
        f16_core<128, E_HALF>(g_xkey16, DM, g_wke16, DM, DM,
                              nullptr, g_k16, nullptr, nullptr, nullptr, DM);
    else if (z == 2)
        f16_core<128, E_HALF>(g_re16, DM, g_wkr16, DM, DM,
                              nullptr, g_qr16, nullptr, nullptr, nullptr, DM);
    else
        f16_core<128, E_VT>(g_xv16, DM, g_wv16, DM, DM,
                            nullptr, g_v16T, nullptr, nullptr, nullptr, SEQ);
}

__global__ __launch_bounds__(256) void einsum16_k() {
    int h = blockIdx.z;
    f16_core<64, E_HALF>(g_w16 + (long)h * SS, SEQ,
                         g_v16T + (long)h * DH * SEQ, SEQ, SEQ,
                         nullptr, g_o116 + h * DH, nullptr, nullptr, nullptr, DM);
}

__global__ __launch_bounds__(256) void final16(float* __restrict__ out) {
    f16_core<64, E_GELU>(g_o116, DM, g_wf16, DM, DM,
                         out, nullptr, nullptr, nullptr, nullptr, DM);
}

// ---------------- stripe-persistent fp16 score kernel ------------------------
// One CTA per (128-row m-stripe, head, mode). A fragments preloaded to regs;
// B tiles double-buffered; output tiles staged in smem, PLAIN coalesced stores
// (ac/bds are re-read by softmax — keep them L2-resident, no __stcs).
#define S_OBOFF (3 * 128 * SRS)

__global__ __launch_bounds__(256) void score_kernel() {
    extern __shared__ char smem[];
    uint32_t sA = smem_u32(smem);
    uint32_t sB = sA + 128 * SRS;

    int tid = threadIdx.x, lane = tid & 31, w = tid >> 5;
    int wm = w >> 1, wn = w & 1;
    int m0 = blockIdx.x * 128;
    int z = blockIdx.y, h = z & (NH - 1), mode = z >> 4;

    const __half* Ag = (mode ? g_qv16 : g_qu16) + h * DH;
    const __half* Bg = (mode ? g_qr16 : g_k16)  + h * DH;
    __half* dst = (mode ? g_bds : g_ac) + (long)h * SS;

#pragma unroll
    for (int i = 0; i < 4; i++) {
        int idx = tid + i * 256;
        int r = idx >> 3, v = idx & 7;
        cp16(sA + r * SRS + v * 16, Ag + (long)(m0 + r) * DM + v * 8);
        cp16(sB + r * SRS + v * 16, Bg + (long)r * DM + v * 8);
    }
    cp_commit();

    uint32_t l15 = (uint32_t)(lane & 15);
    uint32_t lh  = (uint32_t)(lane >> 4);
    uint32_t a[2][4][4];
    const float al = 1.0f / 32.0f;     // 1/sqrt(D_MODEL)
    int rbl = wm * 32 + (lane >> 2);
    int cbl = wn * 64 + (lane & 3) * 2;

    for (int nt = 0; nt < 16; nt++) {
        if (nt + 1 < 16) {
            uint32_t s0 = sB + ((nt + 1) & 1) * (128 * SRS);
            int n0 = (nt + 1) * 128;
#pragma unroll
            for (int i = 0; i < 4; i++) {
                int idx = tid + i * 256;
                int r = idx >> 3, v = idx & 7;
                cp16(s0 + r * SRS + v * 16, Bg + (long)(n0 + r) * DM + v * 8);
            }
            cp_commit();
            cp_wait<1>();
        } else {
            cp_wait<0>();
        }
        __syncthreads();

        if (nt == 0) {
#pragma unroll
            for (int mi = 0; mi < 2; mi++)
#pragma unroll
                for (int ks = 0; ks < 4; ks++)
                    ldmx4(a[mi][ks], sA + (wm * 32 + mi * 16 + l15) * SRS + ks * 32 + lh * 16);
        }

        uint32_t bB = sB + (nt & 1) * (128 * SRS);
        float acc[2][8][4];
#pragma unroll
        for (int mi = 0; mi < 2; mi++)
#pragma unroll
            for (int nj = 0; nj < 8; nj++)
#pragma unroll
                for (int qq = 0; qq < 4; qq++) acc[mi][nj][qq] = 0.0f;

#pragma unroll
        for (int ks = 0; ks < 4; ks++) {
#pragma unroll
            for (int nh = 0; nh < 2; nh++) {
                uint32_t b[2][4];
#pragma unroll
                for (int bt = 0; bt < 2; bt++)
                    ldmx4(b[bt], bB + (wn * 64 + nh * 32 + bt * 16 + l15) * SRS + ks * 32 + lh * 16);
#pragma unroll
                for (int mi = 0; mi < 2; mi++)
#pragma unroll
                    for (int bt = 0; bt < 2; bt++)
#pragma unroll
                        for (int s = 0; s < 2; s++)
                            mma_f16(acc[mi][nh * 4 + bt * 2 + s], a[mi][ks], b[bt][s], b[bt][s + 2]);
            }
        }

#pragma unroll
        for (int mi = 0; mi < 2; mi++)
#pragma unroll
            for (int nj = 0; nj < 8; nj++) {
                int m_l = rbl + mi * 16;
                int n_l = cbl + nj * 8;
                *(__half2*)(smem + S_OBOFF + m_l * OSTR + n_l * 2) =
                    __floats2half2_rn(acc[mi][nj][0] * al, acc[mi][nj][1] * al);
                *(__half2*)(smem + S_OBOFF + (m_l + 8) * OSTR + n_l * 2) =
                    __floats2half2_rn(acc[mi][nj][2] * al, acc[mi][nj][3] * al);
            }
        __syncthreads();

#pragma unroll
        for (int i = 0; i < 8; i++) {
            int idx = tid + i * 256;
            int r = idx >> 4, ch = idx & 15;
            uint4 vv = *(uint4*)(smem + S_OBOFF + r * OSTR + ch * 16);
            *(uint4*)(dst + (long)(m0 + r) * SEQ + nt * 128 + ch * 8) = vv;
        }
    }
}

// ---------------- fused gather-shift + mask + softmax ------------------------
__global__ __launch_bounds__(256) void softmax_kernel(float* __restrict__ w,
                                                      const float* __restrict__ mask) {
    int s = blockIdx.x, h = blockIdx.y;
    long base = ((long)h * SEQ + s) * SEQ;
    const __half* hat = g_bds + (long)h * SS;
    __shared__ float red[8], red2[8];
    int tid = threadIdx.x;
    int lane = tid & 31, wid = tid >> 5;
    int j0 = tid * 8;

    // rel-shift gather geometry (two contiguous runs per row)
    long flat0 = (long)s * SEQ + (SEQ - 1);
    int sp0 = (int)(flat0 / (SEQ + 1));
    int jp0 = (int)(flat0 - (long)sp0 * (SEQ + 1));
    int jwrap = (SEQ + 1) - jp0;
    long base1 = (long)sp0 * SEQ + jp0;
    long base2 = (long)(sp0 + 1) * SEQ - jwrap;

    uint4 acr = __ldcs((const uint4*)(g_ac + base + j0));
    float4 mk0 = *(const float4*)(mask + (long)s * SEQ + j0);
    float4 mk1 = *(const float4*)(mask + (long)s * SEQ + j0 + 4);

    float vals[8];
    {
        const __half2* ah = (const __half2*)&acr;
#pragma unroll
        for (int i = 0; i < 4; i++) {
            float2 a2 = __half22float2(ah[i]);
            vals[2 * i]     = a2.x;
            vals[2 * i + 1] = a2.y;
        }
        const float* mka = (const float*)&mk0;
        const float* mkb = (const float*)&mk1;
#pragma unroll
        for (int i = 0; i < 4; i++) vals[i]     += mka[i];
#pragma unroll
        for (int i = 0; i < 4; i++) vals[4 + i] += mkb[i];

        if (j0 + 8 <= jwrap) {            // fully in run 1 (hole fixed up below)
            const __half* p = hat + base1 + j0;
            if ((base1 & 1) == 0) {       // 4B-aligned: vector loads
                const __half2* p2 = (const __half2*)p;
#pragma unroll
                for (int i = 0; i < 4; i++) {
                    float2 b2 = __half22float2(p2[i]);
                    vals[2 * i]     += b2.x;
                    vals[2 * i + 1] += b2.y;
                }
            } else {
#pragma unroll
                for (int i = 0; i < 8; i++) vals[i] += __half2float(p[i]);
            }
        } else if (j0 >= jwrap) {         // fully in run 2
            const __half* p = hat + base2 + j0;
            if ((base2 & 1) == 0) {
                const __half2* p2 = (const __half2*)p;
#pragma unroll
                for (int i = 0; i < 4; i++) {
                    float2 b2 = __half22float2(p2[i]);
                    vals[2 * i]     += b2.x;
                    vals[2 * i + 1] += b2.y;
                }
            } else {
#pragma unroll
                for (int i = 0; i < 8; i++) vals[i] += __half2float(p[i]);
            }
        } else {                          // straddles the wrap (1 thread per row)
#pragma unroll
            for (int i = 0; i < 8; i++) {
                int j = j0 + i;
                if (j != s + 1)
                    vals[i] += __half2float(hat[(j < jwrap ? base1 : base2) + j]);
            }
        }
        // hole position j == s+1: restore value without bd
        int zp = s + 1 - j0;
        if (zp >= 0 && zp < 8) {
            float2 a2 = __half22float2(((const __half2*)&acr)[zp >> 1]);
            float m = (zp & 4) ? ((const float*)&mk1)[zp & 3] : ((const float*)&mk0)[zp];
            vals[zp] = ((zp & 1) ? a2.y : a2.x) + m;
        }
    }

    float vmax = -3.0e38f;
#pragma unroll
    for (int i = 0; i < 8; i++) vmax = fmaxf(vmax, vals[i]);
    vmax = wred_max(vmax);
    if (lane == 0) red[wid] = vmax;
    __syncthreads();
    vmax = red[0];
#pragma unroll
    for (int i = 1; i < 8; i++) vmax = fmaxf(vmax, red[i]);

    float sum = 0.0f;
#pragma unroll
    for (int i = 0; i < 8; i++) {
        vals[i] = __expf(vals[i] - vmax);
        sum += vals[i];
    }
    sum = wred_sum(sum);
    if (lane == 0) red2[wid] = sum;
    __syncthreads();
    sum = red2[0];
#pragma unroll
    for (int i = 1; i < 8; i++) sum += red2[i];
    float inv = 1.0f / sum;

    float4 o0 = make_float4(vals[0] * inv, vals[1] * inv, vals[2] * inv, vals[3] * inv);
    float4 o1 = make_float4(vals[4] * inv, vals[5] * inv, vals[6] * inv, vals[7] * inv);
    __stcs((float4*)(w + base + j0),     o0);    // w: never re-read -> stream
    __stcs((float4*)(w + base + j0 + 4), o1);

    uint4 h16;
    __half2* hp = (__half2*)&h16;
    hp[0] = __floats2half2_rn(o0.x, o0.y);
    hp[1] = __floats2half2_rn(o0.z, o0.w);
    hp[2] = __floats2half2_rn(o1.x, o1.y);
    hp[3] = __floats2half2_rn(o1.z, o1.w);
    *(uint4*)(g_w16 + base + j0) = h16;          // re-read by einsum -> cache

    if (tid == 0) atomicMax(&g_headmax[h], __float_as_int(inv));
}

__global__ void loss_kernel(float* __restrict__ out) {
    if (threadIdx.x == 0) {
        float s = 0.0f;
        for (int h = 0; h < NH; h++) s += __int_as_float(g_headmax[h]);
        out[(long)SEQ * DM + (long)NH * SS] = s / (float)NH;
    }
}

// ---------------- launcher ---------------------------------------------------
extern "C" void kernel_launch(void* const* d_in, const int* in_sizes, int n_in,
                              void* d_out, int out_size) {
    (void)in_sizes; (void)n_in; (void)out_size;
    const float* query = (const float*)d_in[0];
    const float* key   = (const float*)d_in[1];
    const float* value = (const float*)d_in[2];
    const float* mask  = (const float*)d_in[3];
    const float* Wq    = (const float*)d_in[4];
    const float* Wke   = (const float*)d_in[5];
    const float* Wkr   = (const float*)d_in[6];
    const float* Wv    = (const float*)d_in[7];
    const float* Wf    = (const float*)d_in[8];
    const float* up    = (const float*)d_in[9];
    const float* vp    = (const float*)d_in[10];

    float* out = (float*)d_out;
    float* w   = out + (long)SEQ * DM;

    constexpr int SMEM_P  = 2 * (256 * SRS) + 128 * OSTR;   // 108544 (proj, incl. VT staging)
    constexpr int SMEM_E  = 2 * (192 * SRS);                // 55296 (einsum / final)
    constexpr int SMEM_S  = 3 * 128 * SRS + 128 * OSTR;     // 90112 (score + staging)
    cudaFuncSetAttribute(proj_all16,   cudaFuncAttributeMaxDynamicSharedMemorySize, SMEM_P);
    cudaFuncSetAttribute(einsum16_k,   cudaFuncAttributeMaxDynamicSharedMemorySize, SMEM_E);
    cudaFuncSetAttribute(final16,      cudaFuncAttributeMaxDynamicSharedMemorySize, SMEM_E);
    cudaFuncSetAttribute(score_kernel, cudaFuncAttributeMaxDynamicSharedMemorySize, SMEM_S);

    // 1. merged relenc + fp16 converts (one launch)
    split_all<<<dim3(SEQ * DM / 1024, 1, 9), 256>>>(query, key, value, Wq, Wke, Wkr, Wv, Wf);

    // 2. ALL projections, one fp16 launch (z: q-dual, k, rel, v-transposed)
    proj_all16<<<dim3(DM / 128, SEQ / 128, 4), 256, SMEM_P>>>(up, vp);

    // 3. scores: stripe-persistent fp16, coalesced staged stores (cacheable)
    score_kernel<<<dim3(SEQ / 128, 2 * NH), 256, SMEM_S>>>();

    // 4. fused gather-shift + mask + softmax; emits w (fp32, streamed) + w16 (cached)
    softmax_kernel<<<dim3(SEQ, NH), 256>>>(w, mask);

    // 5. fp16 einsum -> o1 (fp16)
    einsum16_k<<<dim3(1, SEQ / 128, NH), 256, SMEM_E>>>();

    // 6. final projection + exact GELU (fp16 GEMM, fp32 out)
    final16<<<dim3(DM / 64, SEQ / 128), 256, SMEM_E>>>(out);

    // 7. loss scalar
    loss_kernel<<<1, 1>>>(out);
}

// round 16
// speedup vs baseline: 1.1893x; 1.1893x over previous
#include <cuda_runtime.h>
#include <cuda_fp16.h>
#include <math.h>
#include <stdint.h>

#define SEQ 2048
#define DM  1024
#define NH  16
#define DH  64
#define SS  ((long)SEQ * SEQ)

#define SRS  144   // 64 fp16 = 128B data + 16B pad (GEMM staging row stride)
#define OSTR 272   // 128 fp16 = 256B data + 16B pad (output staging row stride)

// ---------------- scratch (device globals; no allocations allowed) ----------
__device__ __half g_bds[(size_t)NH * SEQ * SEQ];            // B_D_hat (unshifted), fp16
__device__ __half g_ac[(size_t)NH * SEQ * SEQ];             // A_C scores, fp16
__device__ __half g_w16[(size_t)NH * SEQ * SEQ];            // softmax weights, fp16

__device__ __half g_xq16[SEQ * DM], g_xkey16[SEQ * DM], g_xv16[SEQ * DM], g_re16[SEQ * DM];
__device__ __half g_wq16[DM * DM], g_wke16[DM * DM], g_wkr16[DM * DM];
__device__ __half g_wv16[DM * DM], g_wf16[DM * DM];

__device__ __half g_qu16[SEQ * DM], g_qv16[SEQ * DM];
__device__ __half g_k16[SEQ * DM],  g_qr16[SEQ * DM];

__device__ __half g_v16T[DM * SEQ];                          // [n=h*64+d][f]
__device__ __half g_o116[SEQ * DM];

__device__ int g_headmax[NH];
__device__ int g_maskflag;                                   // 1 if mask has any nonzero

// ---------------- helpers ----------------------------------------------------
__device__ __forceinline__ uint32_t smem_u32(const void* p) {
    uint32_t a;
    asm("{ .reg .u64 t; cvta.to.shared.u64 t, %1; cvt.u32.u64 %0, t; }" : "=r"(a) : "l"(p));
    return a;
}
__device__ __forceinline__ void cp16(uint32_t s, const void* g) {
    asm volatile("cp.async.cg.shared.global [%0], [%1], 16;" :: "r"(s), "l"(g));
}
__device__ __forceinline__ void cp_commit() {
    asm volatile("cp.async.commit_group;" ::: "memory");
}
template <int N>
__device__ __forceinline__ void cp_wait() {
    asm volatile("cp.async.wait_group %0;" :: "n"(N) : "memory");
}
__device__ __forceinline__ void ldmx4(uint32_t* r, uint32_t addr) {
    asm volatile("ldmatrix.sync.aligned.m8n8.x4.shared.b16 {%0,%1,%2,%3}, [%4];"
                 : "=r"(r[0]), "=r"(r[1]), "=r"(r[2]), "=r"(r[3]) : "r"(addr));
}
__device__ __forceinline__ void mma_f16(float* c, const uint32_t* a, uint32_t b0, uint32_t b1) {
    asm volatile("mma.sync.aligned.m16n8k16.row.col.f32.f16.f16.f32 "
                 "{%0,%1,%2,%3}, {%4,%5,%6,%7}, {%8,%9}, {%0,%1,%2,%3};"
                 : "+f"(c[0]), "+f"(c[1]), "+f"(c[2]), "+f"(c[3])
                 : "r"(a[0]), "r"(a[1]), "r"(a[2]), "r"(a[3]), "r"(b0), "r"(b1));
}
__device__ __forceinline__ float wred_max(float v) {
#pragma unroll
    for (int o = 16; o; o >>= 1) v = fmaxf(v, __shfl_xor_sync(0xFFFFFFFFu, v, o));
    return v;
}
__device__ __forceinline__ float wred_sum(float v) {
#pragma unroll
    for (int o = 16; o; o >>= 1) v += __shfl_xor_sync(0xFFFFFFFFu, v, o);
    return v;
}

struct alignas(8) H4 { __half v[4]; };

// ---------------- merged elementwise fp16 convert + relenc -------------------
__global__ __launch_bounds__(256) void split_all(
    const float* __restrict__ q, const float* __restrict__ k, const float* __restrict__ v,
    const float* __restrict__ wq, const float* __restrict__ wke, const float* __restrict__ wkr,
    const float* __restrict__ wv, const float* __restrict__ wf)
{
    int z = blockIdx.z;
    long i = ((long)blockIdx.x * 256 + threadIdx.x) * 4;
    if (z == 8) {   // relative positional encoding (+ flag inits)
        if (blockIdx.x == 0) {
            if (threadIdx.x < NH) g_headmax[threadIdx.x] = 0;
            if (threadIdx.x == 16) g_maskflag = 0;
        }
        if (i >= (long)SEQ * DM) return;
        int f = (int)(i / DM), c0 = (int)(i % DM);
        float p = (float)(SEQ - 1 - f);
        H4 o;
#pragma unroll
        for (int t = 0; t < 4; t++) {
            int c = c0 + t;
            float e  = (float)(c & ~1) * (1.0f / (float)DM);
            float dv = exp2f(-e * 13.287712379549449f);    // log2(10000)
            float ang = p * dv;
            float s, cs; sincosf(ang, &s, &cs);
            o.v[t] = __float2half((c & 1) ? cs : s);
        }
        *(H4*)(g_re16 + i) = o;
        return;
    }
    long n = (z < 3) ? (long)SEQ * DM : (long)DM * DM;
    if (i >= n) return;
    const float* src; __half* dst;
    switch (z) {
        case 0: src = q;   dst = g_xq16;   break;
        case 1: src = k;   dst = g_xkey16; break;
        case 2: src = v;   dst = g_xv16;   break;
        case 3: src = wq;  dst = g_wq16;   break;
        case 4: src = wke; dst = g_wke16;  break;
        case 5: src = wkr; dst = g_wkr16;  break;
        case 6: src = wv;  dst = g_wv16;   break;
        default: src = wf; dst = g_wf16;   break;
    }
    float4 x = *(const float4*)(src + i);
    H4 o;
    o.v[0] = __float2half(x.x); o.v[1] = __float2half(x.y);
    o.v[2] = __float2half(x.z); o.v[3] = __float2half(x.w);
    *(H4*)(dst + i) = o;
}

// ---------------- mask nonzero check -----------------------------------------
__global__ __launch_bounds__(256) void maskchk(const float* __restrict__ mask) {
    long i = ((long)blockIdx.x * 256 + threadIdx.x) * 4;
    float4 x = *(const float4*)(mask + i);
    bool nz = (x.x != 0.0f) || (x.y != 0.0f) || (x.z != 0.0f) || (x.w != 0.0f);
    if (__ballot_sync(0xFFFFFFFFu, nz)) {
        if ((threadIdx.x & 31) == 0) atomicOr(&g_maskflag, 1);
    }
}

// ---------------- generic fp16 HMMA GEMM core --------------------------------
#define E_HALF 0   // H1[m*ldo+n] = half(x)
#define E_DUAL 1   // H1 = half(x+b1[n]), H2 = half(x+b2[n])
#define E_VT   2   // H1[n*ldo+m] = half(x), via smem-staged transpose
#define E_GELU 3   // outF[m*ldo+n] = gelu(x)

template <int BN, int EPI>
__device__ __forceinline__ void f16_core(
    const __half* __restrict__ Ag, int lda,
    const __half* __restrict__ Bg, int ldb, int K,
    float* __restrict__ outF, __half* __restrict__ H1, __half* __restrict__ H2,
    const float* __restrict__ b1, const float* __restrict__ b2, long ldo)
{
    constexpr int NHT = BN / 64;
    constexpr int NJ  = BN / 16;
    constexpr int STG = (128 + BN) * SRS;
    constexpr int OBOFF = 2 * STG;

    extern __shared__ char smem[];
    uint32_t sb = smem_u32(smem);

    int tid = threadIdx.x, lane = tid & 31, w = tid >> 5;
    int wm = w >> 1, wn = w & 1;
    int m0 = blockIdx.y * 128, n0 = blockIdx.x * BN;

    float acc[2][NJ][4];
#pragma unroll
    for (int mi = 0; mi < 2; mi++)
#pragma unroll
        for (int nj = 0; nj < NJ; nj++)
#pragma unroll
            for (int qq = 0; qq < 4; qq++) acc[mi][nj][qq] = 0.0f;

    auto load_stage = [&](int st, int k0) {
        uint32_t s0 = sb + st * STG;
#pragma unroll
        for (int i = 0; i < 4; i++) {
            int idx = tid + i * 256;
            int r = idx >> 3, v = idx & 7;
            cp16(s0 + r * SRS + v * 16, Ag + (long)(m0 + r) * lda + k0 + v * 8);
        }
#pragma unroll
        for (int i = 0; i < BN / 32; i++) {
            int idx = tid + i * 256;
            int r = idx >> 3, v = idx & 7;
            cp16(s0 + 128 * SRS + r * SRS + v * 16, Bg + (long)(n0 + r) * ldb + k0 + v * 8);
        }
        cp_commit();
    };

    auto compute_stage = [&](int st) {
        uint32_t aB = sb + st * STG;
        uint32_t bB = aB + 128 * SRS;
        uint32_t l15 = (uint32_t)(lane & 15);
        uint32_t lh  = (uint32_t)(lane >> 4);
#pragma unroll
        for (int ks = 0; ks < 4; ks++) {
            uint32_t a[2][4];
#pragma unroll
            for (int mi = 0; mi < 2; mi++)
                ldmx4(a[mi], aB + (wm * 32 + mi * 16 + l15) * SRS + ks * 32 + lh * 16);
#pragma unroll
            for (int nh = 0; nh < NHT; nh++) {
                uint32_t b[2][4];
#pragma unroll
                for (int bt = 0; bt < 2; bt++)
                    ldmx4(b[bt], bB + (wn * (BN / 2) + nh * 32 + bt * 16 + l15) * SRS + ks * 32 + lh * 16);
#pragma unroll
                for (int mi = 0; mi < 2; mi++)
#pragma unroll
                    for (int bt = 0; bt < 2; bt++)
#pragma unroll
                        for (int s = 0; s < 2; s++)
                            mma_f16(acc[mi][nh * 4 + bt * 2 + s], a[mi], b[bt][s], b[bt][s + 2]);
            }
        }
    };

    load_stage(0, 0);
    const int nc = K >> 6;
    for (int c = 0; c < nc; c++) {
        if (c + 1 < nc) {
            load_stage((c + 1) & 1, (c + 1) << 6);
            cp_wait<1>();
        } else {
            cp_wait<0>();
        }
        __syncthreads();
        compute_stage(c & 1);
        __syncthreads();
    }

    int rbl = wm * 32 + (lane >> 2);
    int cbl = wn * (BN / 2) + (lane & 3) * 2;

    if (EPI == E_VT) {
#pragma unroll
        for (int mi = 0; mi < 2; mi++)
#pragma unroll
            for (int nj = 0; nj < NJ; nj++)
#pragma unroll
                for (int qq = 0; qq < 4; qq++) {
                    int m_l = rbl + mi * 16 + (qq >> 1) * 8;
                    int n_l = cbl + nj * 8 + (qq & 1);
                    *(__half*)(smem + OBOFF + n_l * OSTR + m_l * 2) =
                        __float2half(acc[mi][nj][qq]);
                }
        __syncthreads();
#pragma unroll
        for (int i = 0; i < 8; i++) {
            int idx = tid + i * 256;
            int r = idx >> 4, ch = idx & 15;
            uint4 vv = *(uint4*)(smem + OBOFF + r * OSTR + ch * 16);
            *(uint4*)(H1 + (long)(n0 + r) * ldo + m0 + ch * 8) = vv;
        }
        return;
    }

#pragma unroll
    for (int mi = 0; mi < 2; mi++)
#pragma unroll
        for (int nj = 0; nj < NJ; nj++) {
            int m = m0 + rbl + mi * 16;
            int n = n0 + cbl + nj * 8;
            float c0 = acc[mi][nj][0], c1 = acc[mi][nj][1];
            float c2 = acc[mi][nj][2], c3 = acc[mi][nj][3];
            if (EPI == E_HALF) {
                *(__half2*)(H1 + (long)m * ldo + n)       = __floats2half2_rn(c0, c1);
                *(__half2*)(H1 + (long)(m + 8) * ldo + n) = __floats2half2_rn(c2, c3);
            } else if (EPI == E_DUAL) {
                float u0 = b1[n], u1 = b1[n + 1], v0 = b2[n], v1 = b2[n + 1];
                *(__half2*)(H1 + (long)m * ldo + n)       = __floats2half2_rn(c0 + u0, c1 + u1);
                *(__half2*)(H1 + (long)(m + 8) * ldo + n) = __floats2half2_rn(c2 + u0, c3 + u1);
                *(__half2*)(H2 + (long)m * ldo + n)       = __floats2half2_rn(c0 + v0, c1 + v1);
                *(__half2*)(H2 + (long)(m + 8) * ldo + n) = __floats2half2_rn(c2 + v0, c3 + v1);
            } else {  // E_GELU
                float2 o0, o1;
                o0.x = 0.5f * c0 * (1.0f + erff(c0 * 0.70710678118654752440f));
                o0.y = 0.5f * c1 * (1.0f + erff(c1 * 0.70710678118654752440f));
                o1.x = 0.5f * c2 * (1.0f + erff(c2 * 0.70710678118654752440f));
                o1.y = 0.5f * c3 * (1.0f + erff(c3 * 0.70710678118654752440f));
                *(float2*)(outF + (long)m * ldo + n)       = o0;
                *(float2*)(outF + (long)(m + 8) * ldo + n) = o1;
            }
        }
}

// ---------------- GEMM wrapper kernels ---------------------------------------
__global__ __launch_bounds__(256) void proj_all16(const float* __restrict__ up,
                                                  const float* __restrict__ vp) {
    int z = blockIdx.z;
    if (z == 0)
        f16_core<128, E_DUAL>(g_xq16, DM, g_wq16, DM, DM,
                              nullptr, g_qu16, g_qv16, up, vp, DM);
    else if (z == 1)
        f16_core<128, E_HALF>(g_xkey16, DM, g_wke16, DM, DM,
                              nullptr, g_k16, nullptr, nullptr, nullptr, DM);
    else if (z == 2)
        f16_core<128, E_HALF>(g_re16, DM, g_wkr16, DM, DM,
                              nullptr, g_qr16, nullptr, nullptr, nullptr, DM);
    else
        f16_core<128, E_VT>(g_xv16, DM, g_wv16, DM, DM,
                            nullptr, g_v16T, nullptr, nullptr, nullptr, SEQ);
}

__global__ __launch_bounds__(256) void einsum16_k() {
    int h = blockIdx.z;
    f16_core<64, E_HALF>(g_w16 + (long)h * SS, SEQ,
                         g_v16T + (long)h * DH * SEQ, SEQ, SEQ,
                         nullptr, g_o116 + h * DH, nullptr, nullptr, nullptr, DM);
}

__global__ __launch_bounds__(256) void final16(float* __restrict__ out) {
    f16_core<64, E_GELU>(g_o116, DM, g_wf16, DM, DM,
                         out, nullptr, nullptr, nullptr, nullptr, DM);
}

// ---------------- stripe-persistent fp16 score kernel ------------------------
#define S_OBOFF (3 * 128 * SRS)

__global__ __launch_bounds__(256) void score_kernel() {
    extern __shared__ char smem[];
    uint32_t sA = smem_u32(smem);
    uint32_t sB = sA + 128 * SRS;

    int tid = threadIdx.x, lane = tid & 31, w = tid >> 5;
    int wm = w >> 1, wn = w & 1;
    int m0 = blockIdx.x * 128;
    int z = blockIdx.y, h = z & (NH - 1), mode = z >> 4;

    const __half* Ag = (mode ? g_qv16 : g_qu16) + h * DH;
    const __half* Bg = (mode ? g_qr16 : g_k16)  + h * DH;
    __half* dst = (mode ? g_bds : g_ac) + (long)h * SS;

#pragma unroll
    for (int i = 0; i < 4; i++) {
        int idx = tid + i * 256;
        int r = idx >> 3, v = idx & 7;
        cp16(sA + r * SRS + v * 16, Ag + (long)(m0 + r) * DM + v * 8);
        cp16(sB + r * SRS + v * 16, Bg + (long)r * DM + v * 8);
    }
    cp_commit();

    uint32_t l15 = (uint32_t)(lane & 15);
    uint32_t lh  = (uint32_t)(lane >> 4);
    uint32_t a[2][4][4];
    const float al = 1.0f / 32.0f;     // 1/sqrt(D_MODEL)
    int rbl = wm * 32 + (lane >> 2);
    int cbl = wn * 64 + (lane & 3) * 2;

    for (int nt = 0; nt < 16; nt++) {
        if (nt + 1 < 16) {
            uint32_t s0 = sB + ((nt + 1) & 1) * (128 * SRS);
            int n0 = (nt + 1) * 128;
#pragma unroll
            for (int i = 0; i < 4; i++) {
                int idx = tid + i * 256;
                int r = idx >> 3, v = idx & 7;
                cp16(s0 + r * SRS + v * 16, Bg + (long)(n0 + r) * DM + v * 8);
            }
            cp_commit();
            cp_wait<1>();
        } else {
            cp_wait<0>();
        }
        __syncthreads();

        if (nt == 0) {
#pragma unroll
            for (int mi = 0; mi < 2; mi++)
#pragma unroll
                for (int ks = 0; ks < 4; ks++)
                    ldmx4(a[mi][ks], sA + (wm * 32 + mi * 16 + l15) * SRS + ks * 32 + lh * 16);
        }

        uint32_t bB = sB + (nt & 1) * (128 * SRS);
        float acc[2][8][4];
#pragma unroll
        for (int mi = 0; mi < 2; mi++)
#pragma unroll
            for (int nj = 0; nj < 8; nj++)
#pragma unroll
                for (int qq = 0; qq < 4; qq++) acc[mi][nj][qq] = 0.0f;

#pragma unroll
        for (int ks = 0; ks < 4; ks++) {
#pragma unroll
            for (int nh = 0; nh < 2; nh++) {
                uint32_t b[2][4];
#pragma unroll
                for (int bt = 0; bt < 2; bt++)
                    ldmx4(b[bt], bB + (wn * 64 + nh * 32 + bt * 16 + l15) * SRS + ks * 32 + lh * 16);
#pragma unroll
                for (int mi = 0; mi < 2; mi++)
#pragma unroll
                    for (int bt = 0; bt < 2; bt++)
#pragma unroll
                        for (int s = 0; s < 2; s++)
                            mma_f16(acc[mi][nh * 4 + bt * 2 + s], a[mi][ks], b[bt][s], b[bt][s + 2]);
            }
        }

#pragma unroll
        for (int mi = 0; mi < 2; mi++)
#pragma unroll
            for (int nj = 0; nj < 8; nj++) {
                int m_l = rbl + mi * 16;
                int n_l = cbl + nj * 8;
                *(__half2*)(smem + S_OBOFF + m_l * OSTR + n_l * 2) =
                    __floats2half2_rn(acc[mi][nj][0] * al, acc[mi][nj][1] * al);
                *(__half2*)(smem + S_OBOFF + (m_l + 8) * OSTR + n_l * 2) =
                    __floats2half2_rn(acc[mi][nj][2] * al, acc[mi][nj][3] * al);
            }
        __syncthreads();

#pragma unroll
        for (int i = 0; i < 8; i++) {
            int idx = tid + i * 256;
            int r = idx >> 4, ch = idx & 15;
            uint4 vv = *(uint4*)(smem + S_OBOFF + r * OSTR + ch * 16);
            *(uint4*)(dst + (long)(m0 + r) * SEQ + nt * 128 + ch * 8) = vv;
        }
    }
}

// ---------------- fused gather-shift + mask + softmax ------------------------
__global__ __launch_bounds__(256) void softmax_kernel(float* __restrict__ w,
                                                      const float* __restrict__ mask) {
    int s = blockIdx.x, h = blockIdx.y;
    long base = ((long)h * SEQ + s) * SEQ;
    const __half* hat = g_bds + (long)h * SS;
    __shared__ float red[8], red2[8];
    int tid = threadIdx.x;
    int lane = tid & 31, wid = tid >> 5;
    int j0 = tid * 8;
    int mflag = g_maskflag;

    // rel-shift gather geometry (two contiguous runs per row)
    long flat0 = (long)s * SEQ + (SEQ - 1);
    int sp0 = (int)(flat0 / (SEQ + 1));
    int jp0 = (int)(flat0 - (long)sp0 * (SEQ + 1));
    int jwrap = (SEQ + 1) - jp0;
    long base1 = (long)sp0 * SEQ + jp0;
    long base2 = (long)(sp0 + 1) * SEQ - jwrap;

    uint4 acr = __ldcs((const uint4*)(g_ac + base + j0));

    float vals[8];
    {
        const __half2* ah = (const __half2*)&acr;
#pragma unroll
        for (int i = 0; i < 4; i++) {
            float2 a2 = __half22float2(ah[i]);
            vals[2 * i]     = a2.x;
            vals[2 * i + 1] = a2.y;
        }
        if (mflag) {
            float4 mk0 = *(const float4*)(mask + (long)s * SEQ + j0);
            float4 mk1 = *(const float4*)(mask + (long)s * SEQ + j0 + 4);
            vals[0] += mk0.x; vals[1] += mk0.y; vals[2] += mk0.z; vals[3] += mk0.w;
            vals[4] += mk1.x; vals[5] += mk1.y; vals[6] += mk1.z; vals[7] += mk1.w;
        }

        // save hole value (j == s+1 receives NO bd contribution)
        int zp = s + 1 - j0;
        float hole_save = (zp >= 0 && zp < 8) ? vals[zp] : 0.0f;

        if (j0 + 8 <= jwrap) {            // fully in run 1
            const __half* p = hat + base1 + j0;
            if ((base1 & 1) == 0) {
                const __half2* p2 = (const __half2*)p;
#pragma unroll
                for (int i = 0; i < 4; i++) {
                    float2 b2 = __half22float2(p2[i]);
                    vals[2 * i]     += b2.x;
                    vals[2 * i + 1] += b2.y;
                }
            } else {
#pragma unroll
                for (int i = 0; i < 8; i++) vals[i] += __half2float(p[i]);
            }
        } else if (j0 >= jwrap) {         // fully in run 2
            const __half* p = hat + base2 + j0;
            if ((base2 & 1) == 0) {
                const __half2* p2 = (const __half2*)p;
#pragma unroll
                for (int i = 0; i < 4; i++) {
                    float2 b2 = __half22float2(p2[i]);
                    vals[2 * i]     += b2.x;
                    vals[2 * i + 1] += b2.y;
                }
            } else {
#pragma unroll
                for (int i = 0; i < 8; i++) vals[i] += __half2float(p[i]);
            }
        } else {                          // straddles the wrap (1 thread per row)
#pragma unroll
            for (int i = 0; i < 8; i++) {
                int j = j0 + i;
                vals[i] += __half2float(hat[(j < jwrap ? base1 : base2) + j]);
            }
        }
        if (zp >= 0 && zp < 8) vals[zp] = hole_save;   // restore hole
    }

    float vmax = -3.0e38f;
#pragma unroll
    for (int i = 0; i < 8; i++) vmax = fmaxf(vmax, vals[i]);
    vmax = wred_max(vmax);
    if (lane == 0) red[wid] = vmax;
    __syncthreads();
    vmax = red[0];
#pragma unroll
    for (int i = 1; i < 8; i++) vmax = fmaxf(vmax, red[i]);

    float sum = 0.0f;
#pragma unroll
    for (int i = 0; i < 8; i++) {
        vals[i] = __expf(vals[i] - vmax);
        sum += vals[i];
    }
    sum = wred_sum(sum);
    if (lane == 0) red2[wid] = sum;
    __syncthreads();
    sum = red2[0];
#pragma unroll
    for (int i = 1; i < 8; i++) sum += red2[i];
    float inv = 1.0f / sum;

    float4 o0 = make_float4(vals[0] * inv, vals[1] * inv, vals[2] * inv, vals[3] * inv);
    float4 o1 = make_float4(vals[4] * inv, vals[5] * inv, vals[6] * inv, vals[7] * inv);
    __stcs((float4*)(w + base + j0),     o0);    // w: never re-read -> stream
    __stcs((float4*)(w + base + j0 + 4), o1);

    uint4 h16;
    __half2* hp = (__half2*)&h16;
    hp[0] = __floats2half2_rn(o0.x, o0.y);
    hp[1] = __floats2half2_rn(o0.z, o0.w);
    hp[2] = __floats2half2_rn(o1.x, o1.y);
    hp[3] = __floats2half2_rn(o1.z, o1.w);
    *(uint4*)(g_w16 + base + j0) = h16;          // re-read by einsum -> cache

    if (tid == 0) atomicMax(&g_headmax[h], __float_as_int(inv));
}

__global__ void loss_kernel(float* __restrict__ out) {
    if (threadIdx.x == 0) {
        float s = 0.0f;
        for (int h = 0; h < NH; h++) s += __int_as_float(g_headmax[h]);
        out[(long)SEQ * DM + (long)NH * SS] = s / (float)NH;
    }
}

// ---------------- launcher ---------------------------------------------------
extern "C" void kernel_launch(void* const* d_in, const int* in_sizes, int n_in,
                              void* d_out, int out_size) {
    (void)in_sizes; (void)n_in; (void)out_size;
    const float* query = (const float*)d_in[0];
    const float* key   = (const float*)d_in[1];
    const float* value = (const float*)d_in[2];
    const float* mask  = (const float*)d_in[3];
    const float* Wq    = (const float*)d_in[4];
    const float* Wke   = (const float*)d_in[5];
    const float* Wkr   = (const float*)d_in[6];
    const float* Wv    = (const float*)d_in[7];
    const float* Wf    = (const float*)d_in[8];
    const float* up    = (const float*)d_in[9];
    const float* vp    = (const float*)d_in[10];

    float* out = (float*)d_out;
    float* w   = out + (long)SEQ * DM;

    constexpr int SMEM_P  = 2 * (256 * SRS) + 128 * OSTR;   // 108544 (proj, incl. VT staging)
    constexpr int SMEM_E  = 2 * (192 * SRS);                // 55296 (einsum / final)
    constexpr int SMEM_S  = 3 * 128 * SRS + 128 * OSTR;     // 90112 (score + staging)
    cudaFuncSetAttribute(proj_all16,   cudaFuncAttributeMaxDynamicSharedMemorySize, SMEM_P);
    cudaFuncSetAttribute(einsum16_k,   cudaFuncAttributeMaxDynamicSharedMemorySize, SMEM_E);
    cudaFuncSetAttribute(final16,      cudaFuncAttributeMaxDynamicSharedMemorySize, SMEM_E);
    cudaFuncSetAttribute(score_kernel, cudaFuncAttributeMaxDynamicSharedMemorySize, SMEM_S);

    // 1. merged relenc + fp16 converts (one launch), then mask nonzero check
    split_all<<<dim3(SEQ * DM / 1024, 1, 9), 256>>>(query, key, value, Wq, Wke, Wkr, Wv, Wf);
    maskchk<<<SEQ * SEQ / 1024, 256>>>(mask);

    // 2. ALL projections, one fp16 launch (z: q-dual, k, rel, v-transposed)
    proj_all16<<<dim3(DM / 128, SEQ / 128, 4), 256, SMEM_P>>>(up, vp);

    // 3. scores: stripe-persistent fp16, coalesced staged stores
    score_kernel<<<dim3(SEQ / 128, 2 * NH), 256, SMEM_S>>>();

    // 4. fused gather-shift + softmax (mask skipped when identically zero)
    softmax_kernel<<<dim3(SEQ, NH), 256>>>(w, mask);

    // 5. fp16 einsum -> o1 (fp16)
    einsum16_k<<<dim3(1, SEQ / 128, NH), 256, SMEM_E>>>();

    // 6. final projection + exact GELU (fp16 GEMM, fp32 out)
    final16<<<dim3(DM / 64, SEQ / 128), 256, SMEM_E>>>(out);

    // 7. loss scalar
    loss_kernel<<<1, 1>>>(out);
}